// round 2
// baseline (speedup 1.0000x reference)
#include <cuda_runtime.h>
#include <cstdint>

#define NTOK   4096
#define DMODEL 1024
#define NEXP   8
#define TOPK   2
#define HEXP   704
#define HSH    1408

#define BM 128
#define BN 64
#define BK 16
#define ASTR 20     // As row stride (words): conflict-free fragment loads
#define BSTR 72     // Bs row stride (words): conflict-free fragment loads

// ---------------- scratch (device globals; no allocation allowed) ----------
__device__ int   g_cnt[NEXP];
__device__ int   g_off[NEXP + 1];
__device__ int   g_cur[NEXP];
__device__ int   g_topi[NTOK * TOPK];
__device__ float g_topw[NTOK * TOPK];
__device__ int   g_tok[NTOK * TOPK];
__device__ float g_gate[NTOK * TOPK];
__device__ float g_hid_r[NTOK * TOPK * HEXP];   // routed SwiGLU hidden
__device__ float g_hid_s[NTOK * HSH];           // shared-expert hidden

// ---------------- tiny setup kernels ---------------------------------------
__global__ void zero_kernel() {
    int t = threadIdx.x;
    if (t < NEXP) { g_cnt[t] = 0; g_cur[t] = 0; }
}

__global__ void scan_kernel() {
    int acc = 0;
    g_off[0] = 0;
    for (int e = 0; e < NEXP; e++) { acc += g_cnt[e]; g_off[e + 1] = acc; }
}

__global__ void router_kernel(const float* __restrict__ x,
                              const float* __restrict__ Wg) {
    int gw   = (blockIdx.x * blockDim.x + threadIdx.x) >> 5;
    int lane = threadIdx.x & 31;
    if (gw >= NTOK) return;
    const float* xr = x + (size_t)gw * DMODEL;

    float acc[NEXP];
#pragma unroll
    for (int e = 0; e < NEXP; e++) acc[e] = 0.f;
    for (int k = lane; k < DMODEL; k += 32) {
        float xv = xr[k];
#pragma unroll
        for (int e = 0; e < NEXP; e++) acc[e] += xv * Wg[e * DMODEL + k];
    }
#pragma unroll
    for (int e = 0; e < NEXP; e++) {
#pragma unroll
        for (int o = 16; o > 0; o >>= 1)
            acc[e] += __shfl_xor_sync(0xffffffffu, acc[e], o);
    }
    if (lane == 0) {
        float m = acc[0];
#pragma unroll
        for (int e = 1; e < NEXP; e++) m = fmaxf(m, acc[e]);
        float p[NEXP], s = 0.f;
#pragma unroll
        for (int e = 0; e < NEXP; e++) { p[e] = expf(acc[e] - m); s += p[e]; }
        float inv = 1.f / s;
#pragma unroll
        for (int e = 0; e < NEXP; e++) p[e] *= inv;

        int i0 = 0; float v0 = p[0];
#pragma unroll
        for (int e = 1; e < NEXP; e++) if (p[e] > v0) { v0 = p[e]; i0 = e; }
        int i1 = (i0 == 0) ? 1 : 0; float v1 = p[i1];
#pragma unroll
        for (int e = 0; e < NEXP; e++)
            if (e != i0 && p[e] > v1) { v1 = p[e]; i1 = e; }

        float sw = v0 + v1 + 1e-20f;
        g_topi[gw * 2]     = i0;  g_topi[gw * 2 + 1] = i1;
        g_topw[gw * 2]     = v0 / sw;  g_topw[gw * 2 + 1] = v1 / sw;
        atomicAdd(&g_cnt[i0], 1);
        atomicAdd(&g_cnt[i1], 1);
    }
}

__global__ void fill_kernel() {
    int n = blockIdx.x * blockDim.x + threadIdx.x;
    if (n >= NTOK) return;
#pragma unroll
    for (int s = 0; s < TOPK; s++) {
        int e   = g_topi[n * 2 + s];
        int pos = atomicAdd(&g_cur[e], 1);
        int idx = g_off[e] + pos;
        g_tok[idx]  = n;
        g_gate[idx] = g_topw[n * 2 + s];
    }
}

__device__ __forceinline__ float silu_f(float z) {
    return z / (1.f + __expf(-z));
}

__device__ __forceinline__ uint32_t f2tf32(float f) {
    uint32_t u;
    asm("cvt.rna.tf32.f32 %0, %1;" : "=r"(u) : "f"(f));
    return u;
}

__device__ __forceinline__ void mma_tf32(float* c, const uint32_t* a,
                                         uint32_t b0, uint32_t b1) {
    asm volatile(
        "mma.sync.aligned.m16n8k8.row.col.f32.tf32.tf32.f32 "
        "{%0,%1,%2,%3}, {%4,%5,%6,%7}, {%8,%9}, {%0,%1,%2,%3};\n"
        : "+f"(c[0]), "+f"(c[1]), "+f"(c[2]), "+f"(c[3])
        : "r"(a[0]), "r"(a[1]), "r"(a[2]), "r"(a[3]), "r"(b0), "r"(b1));
}

// ============ SwiGLU up-proj: hid = silu(A@W1) * (A@W3) =====================
// A rows gathered via g_tok (ROUTED) or identity (shared). K = DMODEL.
template<bool ROUTED>
__global__ __launch_bounds__(256, 2)
void swiglu_mma(const float* __restrict__ x,
                const float* __restrict__ W1g,
                const float* __restrict__ W3g,
                float* __restrict__ hid, int H) {
    int e = 0, base = 0, ne = NTOK;
    if (ROUTED) { e = blockIdx.z; base = g_off[e]; ne = g_off[e + 1] - base; }
    int m0 = blockIdx.y * BM;
    if (m0 >= ne) return;
    int n0 = blockIdx.x * BN;

    const float* W1 = W1g + (ROUTED ? (size_t)e * DMODEL * H : 0) + n0;
    const float* W3 = W3g + (ROUTED ? (size_t)e * DMODEL * H : 0) + n0;

    __shared__ uint32_t As[BM][ASTR];
    __shared__ uint32_t Bs1[BK][BSTR];
    __shared__ uint32_t Bs3[BK][BSTR];
    __shared__ int      stok[BM];

    int tid = threadIdx.x;
    if (ROUTED) {
        if (tid < BM) stok[tid] = (m0 + tid < ne) ? g_tok[base + m0 + tid] : -1;
        __syncthreads();
    }

    // A loader: thread -> (row = tid>>1, k-half = (tid&1)*8), 2 float4
    int arow = tid >> 1;
    int ak0  = (tid & 1) * 8;
    bool aok;
    const float* Arow;
    if (ROUTED) {
        int tk = stok[arow];
        aok  = (tk >= 0);
        Arow = x + (size_t)(aok ? tk : 0) * DMODEL;
    } else {
        aok  = true;
        Arow = x + (size_t)(m0 + arow) * DMODEL;
    }
    // B loader: thread -> (krow = tid>>4, n4 = (tid&15)*4), 1 float4 each matrix
    int bk = tid >> 4;
    int bn = (tid & 15) * 4;

    float4 aA = make_float4(0,0,0,0), aB = make_float4(0,0,0,0);
    if (aok) {
        aA = *(const float4*)(Arow + ak0);
        aB = *(const float4*)(Arow + ak0 + 4);
    }
    float4 bv1 = *(const float4*)(W1 + (size_t)bk * H + bn);
    float4 bv3 = *(const float4*)(W3 + (size_t)bk * H + bn);

    int lane = tid & 31, wid = tid >> 5;
    int mw = (wid & 3) * 32, nw = (wid >> 2) * 32;
    int g = lane >> 2, tq = lane & 3;

    float acc1[2][4][4], acc3[2][4][4];
#pragma unroll
    for (int i = 0; i < 2; i++)
#pragma unroll
        for (int j = 0; j < 4; j++)
#pragma unroll
            for (int k = 0; k < 4; k++) { acc1[i][j][k] = 0.f; acc3[i][j][k] = 0.f; }

    for (int kk = 0; kk < DMODEL; kk += BK) {
        As[arow][ak0 + 0] = f2tf32(aA.x);
        As[arow][ak0 + 1] = f2tf32(aA.y);
        As[arow][ak0 + 2] = f2tf32(aA.z);
        As[arow][ak0 + 3] = f2tf32(aA.w);
        As[arow][ak0 + 4] = f2tf32(aB.x);
        As[arow][ak0 + 5] = f2tf32(aB.y);
        As[arow][ak0 + 6] = f2tf32(aB.z);
        As[arow][ak0 + 7] = f2tf32(aB.w);
        Bs1[bk][bn + 0] = f2tf32(bv1.x);
        Bs1[bk][bn + 1] = f2tf32(bv1.y);
        Bs1[bk][bn + 2] = f2tf32(bv1.z);
        Bs1[bk][bn + 3] = f2tf32(bv1.w);
        Bs3[bk][bn + 0] = f2tf32(bv3.x);
        Bs3[bk][bn + 1] = f2tf32(bv3.y);
        Bs3[bk][bn + 2] = f2tf32(bv3.z);
        Bs3[bk][bn + 3] = f2tf32(bv3.w);
        __syncthreads();

        int kn = kk + BK;
        if (kn < DMODEL) {
            if (aok) {
                aA = *(const float4*)(Arow + kn + ak0);
                aB = *(const float4*)(Arow + kn + ak0 + 4);
            }
            bv1 = *(const float4*)(W1 + (size_t)(kn + bk) * H + bn);
            bv3 = *(const float4*)(W3 + (size_t)(kn + bk) * H + bn);
        }

#pragma unroll
        for (int ks = 0; ks < 2; ks++) {
            uint32_t a[2][4];
#pragma unroll
            for (int mt = 0; mt < 2; mt++) {
                int r = mw + mt * 16 + g;
                a[mt][0] = As[r][ks * 8 + tq];
                a[mt][1] = As[r + 8][ks * 8 + tq];
                a[mt][2] = As[r][ks * 8 + tq + 4];
                a[mt][3] = As[r + 8][ks * 8 + tq + 4];
            }
#pragma unroll
            for (int nt = 0; nt < 4; nt++) {
                int c = nw + nt * 8 + g;
                uint32_t p0 = Bs1[ks * 8 + tq][c];
                uint32_t p1 = Bs1[ks * 8 + tq + 4][c];
                uint32_t q0 = Bs3[ks * 8 + tq][c];
                uint32_t q1 = Bs3[ks * 8 + tq + 4][c];
#pragma unroll
                for (int mt = 0; mt < 2; mt++) {
                    mma_tf32(acc1[mt][nt], a[mt], p0, p1);
                    mma_tf32(acc3[mt][nt], a[mt], q0, q1);
                }
            }
        }
        __syncthreads();
    }

#pragma unroll
    for (int mt = 0; mt < 2; mt++) {
#pragma unroll
        for (int h = 0; h < 2; h++) {
            int r = mw + mt * 16 + g + h * 8;
            if (!ROUTED || (m0 + r < ne)) {
                size_t rowoff = (size_t)(base + m0 + r) * H + n0;
#pragma unroll
                for (int nt = 0; nt < 4; nt++) {
                    int col = nw + nt * 8 + 2 * tq;
                    float2 v;
                    v.x = silu_f(acc1[mt][nt][2 * h])     * acc3[mt][nt][2 * h];
                    v.y = silu_f(acc1[mt][nt][2 * h + 1]) * acc3[mt][nt][2 * h + 1];
                    *(float2*)&hid[rowoff + col] = v;
                }
            }
        }
    }
}

// ============ Down-proj: out (+)= gate * (hid @ W2). K = H ==================
template<bool ROUTED>
__global__ __launch_bounds__(256, 2)
void down_mma(const float* __restrict__ hidg,
              const float* __restrict__ W2g,
              float* __restrict__ out, int K) {
    int e = 0, base = 0, ne = NTOK;
    if (ROUTED) { e = blockIdx.z; base = g_off[e]; ne = g_off[e + 1] - base; }
    int m0 = blockIdx.y * BM;
    if (m0 >= ne) return;
    int n0 = blockIdx.x * BN;

    const float* W2 = W2g + (ROUTED ? (size_t)e * K * DMODEL : 0) + n0;

    __shared__ uint32_t As[BM][ASTR];
    __shared__ uint32_t Bs[BK][BSTR];
    __shared__ int      stok[BM];
    __shared__ float    sgate[BM];

    int tid = threadIdx.x;
    if (ROUTED) {
        if (tid < BM) {
            bool v = (m0 + tid < ne);
            stok[tid]  = v ? g_tok[base + m0 + tid] : 0;
            sgate[tid] = v ? g_gate[base + m0 + tid] : 0.f;
        }
        __syncthreads();
    }

    int arow = tid >> 1;
    int ak0  = (tid & 1) * 8;
    bool aok = (m0 + arow < ne);
    const float* Arow = hidg + (size_t)(base + m0 + (aok ? arow : 0)) * K;
    int bk = tid >> 4;
    int bn = (tid & 15) * 4;

    float4 aA = make_float4(0,0,0,0), aB = make_float4(0,0,0,0);
    if (aok) {
        aA = *(const float4*)(Arow + ak0);
        aB = *(const float4*)(Arow + ak0 + 4);
    }
    float4 bv = *(const float4*)(W2 + (size_t)bk * DMODEL + bn);

    int lane = tid & 31, wid = tid >> 5;
    int mw = (wid & 3) * 32, nw = (wid >> 2) * 32;
    int g = lane >> 2, tq = lane & 3;

    float acc[2][4][4];
#pragma unroll
    for (int i = 0; i < 2; i++)
#pragma unroll
        for (int j = 0; j < 4; j++)
#pragma unroll
            for (int k = 0; k < 4; k++) acc[i][j][k] = 0.f;

    for (int kk = 0; kk < K; kk += BK) {
        As[arow][ak0 + 0] = f2tf32(aA.x);
        As[arow][ak0 + 1] = f2tf32(aA.y);
        As[arow][ak0 + 2] = f2tf32(aA.z);
        As[arow][ak0 + 3] = f2tf32(aA.w);
        As[arow][ak0 + 4] = f2tf32(aB.x);
        As[arow][ak0 + 5] = f2tf32(aB.y);
        As[arow][ak0 + 6] = f2tf32(aB.z);
        As[arow][ak0 + 7] = f2tf32(aB.w);
        Bs[bk][bn + 0] = f2tf32(bv.x);
        Bs[bk][bn + 1] = f2tf32(bv.y);
        Bs[bk][bn + 2] = f2tf32(bv.z);
        Bs[bk][bn + 3] = f2tf32(bv.w);
        __syncthreads();

        int kn = kk + BK;
        if (kn < K) {
            if (aok) {
                aA = *(const float4*)(Arow + kn + ak0);
                aB = *(const float4*)(Arow + kn + ak0 + 4);
            }
            bv = *(const float4*)(W2 + (size_t)(kn + bk) * DMODEL + bn);
        }

#pragma unroll
        for (int ks = 0; ks < 2; ks++) {
            uint32_t a[2][4];
#pragma unroll
            for (int mt = 0; mt < 2; mt++) {
                int r = mw + mt * 16 + g;
                a[mt][0] = As[r][ks * 8 + tq];
                a[mt][1] = As[r + 8][ks * 8 + tq];
                a[mt][2] = As[r][ks * 8 + tq + 4];
                a[mt][3] = As[r + 8][ks * 8 + tq + 4];
            }
#pragma unroll
            for (int nt = 0; nt < 4; nt++) {
                int c = nw + nt * 8 + g;
                uint32_t p0 = Bs[ks * 8 + tq][c];
                uint32_t p1 = Bs[ks * 8 + tq + 4][c];
#pragma unroll
                for (int mt = 0; mt < 2; mt++)
                    mma_tf32(acc[mt][nt], a[mt], p0, p1);
            }
        }
        __syncthreads();
    }

#pragma unroll
    for (int mt = 0; mt < 2; mt++) {
#pragma unroll
        for (int h = 0; h < 2; h++) {
            int r = mw + mt * 16 + g + h * 8;
            if (ROUTED) {
                if (m0 + r < ne) {
                    int   tk = stok[r];
                    float w  = sgate[r];
                    float* op = out + (size_t)tk * DMODEL + n0;
#pragma unroll
                    for (int nt = 0; nt < 4; nt++) {
                        int col = nw + nt * 8 + 2 * tq;
                        atomicAdd(op + col,     w * acc[mt][nt][2 * h]);
                        atomicAdd(op + col + 1, w * acc[mt][nt][2 * h + 1]);
                    }
                }
            } else {
                size_t rowoff = (size_t)(m0 + r) * DMODEL + n0;
#pragma unroll
                for (int nt = 0; nt < 4; nt++) {
                    int col = nw + nt * 8 + 2 * tq;
                    float2 v;
                    v.x = acc[mt][nt][2 * h];
                    v.y = acc[mt][nt][2 * h + 1];
                    *(float2*)&out[rowoff + col] = v;
                }
            }
        }
    }
}

// ---------------- launch ----------------------------------------------------
extern "C" void kernel_launch(void* const* d_in, const int* in_sizes, int n_in,
                              void* d_out, int out_size) {
    const float* x   = (const float*)d_in[0];
    const float* Wg  = (const float*)d_in[1];
    const float* W1  = (const float*)d_in[2];
    const float* W3  = (const float*)d_in[3];
    const float* W2  = (const float*)d_in[4];
    const float* Ws1 = (const float*)d_in[5];
    const float* Ws3 = (const float*)d_in[6];
    const float* Ws2 = (const float*)d_in[7];
    float* out = (float*)d_out;

    zero_kernel<<<1, 32>>>();
    router_kernel<<<NTOK / 8, 256>>>(x, Wg);
    scan_kernel<<<1, 1>>>();
    fill_kernel<<<NTOK / 256, 256>>>();

    // shared expert writes every element of out -> must precede routed scatter
    swiglu_mma<false><<<dim3(HSH / BN, NTOK / BM), 256>>>(x, Ws1, Ws3, g_hid_s, HSH);
    down_mma<false><<<dim3(DMODEL / BN, NTOK / BM), 256>>>(g_hid_s, Ws2, out, HSH);

    swiglu_mma<true><<<dim3(HEXP / BN, NTOK / BM, NEXP), 256>>>(x, W1, W3, g_hid_r, HEXP);
    down_mma<true><<<dim3(DMODEL / BN, NTOK / BM, NEXP), 256>>>(g_hid_r, W2, out, HEXP);
}

// round 5
// speedup vs baseline: 2.7707x; 2.7707x over previous
#include <cuda_runtime.h>
#include <cstdint>

#define NTOK   4096
#define DMODEL 1024
#define NEXP   8
#define TOPK   2
#define HEXP   704
#define HSH    1408

#define BM 64
#define BN 64
#define BK 16
#define NTHREADS 256

typedef unsigned long long u64;

// ---------------- scratch (device globals; no allocation allowed) ----------
__device__ int   g_cnt[NEXP];
__device__ int   g_off[NEXP + 1];
__device__ int   g_cur[NEXP];
__device__ int   g_topi[NTOK * TOPK];
__device__ float g_topw[NTOK * TOPK];
__device__ int   g_tok[NTOK * TOPK];
__device__ float g_gate[NTOK * TOPK];
__device__ float g_hid_r[NTOK * TOPK * HEXP];   // routed SwiGLU hidden
__device__ float g_hid_s[NTOK * HSH];           // shared-expert hidden

// ---------------- f32x2 helpers (explicit packing, no type punning) --------
__device__ __forceinline__ void fma2(u64& d, u64 a, u64 b) {
    asm("fma.rn.f32x2 %0, %1, %2, %0;" : "+l"(d) : "l"(a), "l"(b));
}
__device__ __forceinline__ u64 packf2(float lo, float hi) {
    u64 d;
    asm("mov.b64 %0, {%1, %2};" : "=l"(d) : "f"(lo), "f"(hi));
    return d;
}
__device__ __forceinline__ u64 splat2(float a) {
    u64 d;
    asm("mov.b64 %0, {%1, %1};" : "=l"(d) : "f"(a));
    return d;
}
__device__ __forceinline__ float2 unpack2(u64 v) {
    float2 r;
    asm("mov.b64 {%0, %1}, %2;" : "=f"(r.x), "=f"(r.y) : "l"(v));
    return r;
}

// ---------------- tiny setup kernels ---------------------------------------
__global__ void zero_kernel() {
    int t = threadIdx.x;
    if (t < NEXP) { g_cnt[t] = 0; g_cur[t] = 0; }
}

__global__ void scan_kernel() {
    int acc = 0;
    g_off[0] = 0;
    for (int e = 0; e < NEXP; e++) { acc += g_cnt[e]; g_off[e + 1] = acc; }
}

// one warp per token: logits -> softmax -> top2 -> normalized gates
__global__ void router_kernel(const float* __restrict__ x,
                              const float* __restrict__ Wg) {
    int gw   = (blockIdx.x * blockDim.x + threadIdx.x) >> 5;
    int lane = threadIdx.x & 31;
    if (gw >= NTOK) return;
    const float* xr = x + (size_t)gw * DMODEL;

    float acc[NEXP];
#pragma unroll
    for (int e = 0; e < NEXP; e++) acc[e] = 0.f;

    for (int k = lane; k < DMODEL; k += 32) {
        float xv = xr[k];
#pragma unroll
        for (int e = 0; e < NEXP; e++) acc[e] += xv * Wg[e * DMODEL + k];
    }
#pragma unroll
    for (int e = 0; e < NEXP; e++) {
#pragma unroll
        for (int o = 16; o > 0; o >>= 1)
            acc[e] += __shfl_xor_sync(0xffffffffu, acc[e], o);
    }
    if (lane == 0) {
        float m = acc[0];
#pragma unroll
        for (int e = 1; e < NEXP; e++) m = fmaxf(m, acc[e]);
        float p[NEXP], s = 0.f;
#pragma unroll
        for (int e = 0; e < NEXP; e++) { p[e] = expf(acc[e] - m); s += p[e]; }
        float inv = 1.f / s;
#pragma unroll
        for (int e = 0; e < NEXP; e++) p[e] *= inv;

        int   i0 = 0; float v0 = p[0];
#pragma unroll
        for (int e = 1; e < NEXP; e++) if (p[e] > v0) { v0 = p[e]; i0 = e; }
        int   i1 = (i0 == 0) ? 1 : 0; float v1 = p[i1];
#pragma unroll
        for (int e = 0; e < NEXP; e++)
            if (e != i0 && p[e] > v1) { v1 = p[e]; i1 = e; }

        float sw = v0 + v1 + 1e-20f;
        float w0 = v0 / sw, w1 = v1 / sw;
        g_topi[gw * 2]     = i0;  g_topi[gw * 2 + 1] = i1;
        g_topw[gw * 2]     = w0;  g_topw[gw * 2 + 1] = w1;
        atomicAdd(&g_cnt[i0], 1);
        atomicAdd(&g_cnt[i1], 1);
    }
}

__global__ void fill_kernel() {
    int n = blockIdx.x * blockDim.x + threadIdx.x;
    if (n >= NTOK) return;
#pragma unroll
    for (int s = 0; s < TOPK; s++) {
        int e   = g_topi[n * 2 + s];
        int pos = atomicAdd(&g_cur[e], 1);
        int idx = g_off[e] + pos;
        g_tok[idx]  = n;
        g_gate[idx] = g_topw[n * 2 + s];
    }
}

__device__ __forceinline__ float silu_f(float z) {
    return z / (1.f + __expf(-z));
}

// ---------------- GEMM1 routed: H = silu(Xg@W1e) * (Xg@W3e) ----------------
// grid: (HEXP/BN=11, NTOK/BM=64, NEXP), block 256
__global__ __launch_bounds__(NTHREADS)
void gemm1_routed(const float* __restrict__ x,
                  const float* __restrict__ W1,
                  const float* __restrict__ W3) {
    int e    = blockIdx.z;
    int base = g_off[e];
    int ne   = g_off[e + 1] - base;
    int m0   = blockIdx.y * BM;
    if (m0 >= ne) return;
    int n0 = blockIdx.x * BN;

    __shared__ float As[BK][BM + 4];
    __shared__ float Bs1[BK][BN];
    __shared__ float Bs3[BK][BN];
    __shared__ int   stok[BM];

    int tid = threadIdx.x;
    if (tid < BM) stok[tid] = (m0 + tid < ne) ? g_tok[base + m0 + tid] : -1;
    __syncthreads();

    const float* B1 = W1 + (size_t)e * DMODEL * HEXP + n0;
    const float* B3 = W3 + (size_t)e * DMODEL * HEXP + n0;

    int ar = tid >> 2, ac = (tid & 3) * 4;
    int br = tid >> 4, bc = (tid & 15) * 4;
    int atok = stok[ar];
    const float* Aptr = (atok >= 0) ? (x + (size_t)atok * DMODEL + ac) : 0;

    float4 av = make_float4(0.f, 0.f, 0.f, 0.f);
    if (Aptr) av = *(const float4*)Aptr;
    float4 b1v = *(const float4*)(B1 + (size_t)br * HEXP + bc);
    float4 b3v = *(const float4*)(B3 + (size_t)br * HEXP + bc);

    int tm0 = (tid >> 4) * 4, tn0 = (tid & 15) * 4;
    u64 acc1[4][2], acc3[4][2];
#pragma unroll
    for (int i = 0; i < 4; i++)
#pragma unroll
        for (int j = 0; j < 2; j++) { acc1[i][j] = 0ull; acc3[i][j] = 0ull; }

    for (int kk = 0; kk < DMODEL; kk += BK) {
        As[ac + 0][ar] = av.x; As[ac + 1][ar] = av.y;
        As[ac + 2][ar] = av.z; As[ac + 3][ar] = av.w;
        *(float4*)&Bs1[br][bc] = b1v;
        *(float4*)&Bs3[br][bc] = b3v;
        __syncthreads();
        int kn = kk + BK;
        if (kn < DMODEL) {
            if (Aptr) av = *(const float4*)(Aptr + kn);
            b1v = *(const float4*)(B1 + (size_t)(kn + br) * HEXP + bc);
            b3v = *(const float4*)(B3 + (size_t)(kn + br) * HEXP + bc);
        }
#pragma unroll
        for (int k = 0; k < BK; k++) {
            float4 a  = *(const float4*)&As[k][tm0];
            float4 b1 = *(const float4*)&Bs1[k][tn0];
            float4 b3 = *(const float4*)&Bs3[k][tn0];
            u64 b1p0 = packf2(b1.x, b1.y), b1p1 = packf2(b1.z, b1.w);
            u64 b3p0 = packf2(b3.x, b3.y), b3p1 = packf2(b3.z, b3.w);
            u64 a2[4];
            a2[0] = splat2(a.x); a2[1] = splat2(a.y);
            a2[2] = splat2(a.z); a2[3] = splat2(a.w);
#pragma unroll
            for (int i = 0; i < 4; i++) {
                fma2(acc1[i][0], a2[i], b1p0);
                fma2(acc1[i][1], a2[i], b1p1);
                fma2(acc3[i][0], a2[i], b3p0);
                fma2(acc3[i][1], a2[i], b3p1);
            }
        }
        __syncthreads();
    }
#pragma unroll
    for (int i = 0; i < 4; i++) {
        int r = tm0 + i;
        if (m0 + r < ne) {
            float2 h0 = unpack2(acc1[i][0]), h1 = unpack2(acc1[i][1]);
            float2 q0 = unpack2(acc3[i][0]), q1 = unpack2(acc3[i][1]);
            float4 hv;
            hv.x = silu_f(h0.x) * q0.x;
            hv.y = silu_f(h0.y) * q0.y;
            hv.z = silu_f(h1.x) * q1.x;
            hv.w = silu_f(h1.y) * q1.y;
            *(float4*)&g_hid_r[(size_t)(base + m0 + r) * HEXP + n0 + tn0] = hv;
        }
    }
}

// ---------------- GEMM2 routed: out += gate * (H @ W2e), scatter -----------
// grid: (DMODEL/BN=16, NTOK/BM=64, NEXP)
__global__ __launch_bounds__(NTHREADS)
void gemm2_routed(const float* __restrict__ W2, float* __restrict__ out) {
    int e    = blockIdx.z;
    int base = g_off[e];
    int ne   = g_off[e + 1] - base;
    int m0   = blockIdx.y * BM;
    if (m0 >= ne) return;
    int n0 = blockIdx.x * BN;

    __shared__ float As[BK][BM + 4];
    __shared__ float Bs[BK][BN];
    __shared__ int   stok[BM];
    __shared__ float sgate[BM];

    int tid = threadIdx.x;
    if (tid < BM) {
        bool v = (m0 + tid < ne);
        stok[tid]  = v ? g_tok[base + m0 + tid] : -1;
        sgate[tid] = v ? g_gate[base + m0 + tid] : 0.f;
    }
    __syncthreads();

    const float* Bp = W2 + (size_t)e * HEXP * DMODEL + n0;

    int ar = tid >> 2, ac = (tid & 3) * 4;
    int br = tid >> 4, bc = (tid & 15) * 4;
    bool arow_ok = (m0 + ar < ne);
    const float* Aptr = g_hid_r + (size_t)(base + m0 + ar) * HEXP + ac;

    float4 av = make_float4(0.f, 0.f, 0.f, 0.f);
    if (arow_ok) av = *(const float4*)Aptr;
    float4 bv = *(const float4*)(Bp + (size_t)br * DMODEL + bc);

    int tm0 = (tid >> 4) * 4, tn0 = (tid & 15) * 4;
    u64 acc[4][2];
#pragma unroll
    for (int i = 0; i < 4; i++) { acc[i][0] = 0ull; acc[i][1] = 0ull; }

    for (int kk = 0; kk < HEXP; kk += BK) {
        As[ac + 0][ar] = av.x; As[ac + 1][ar] = av.y;
        As[ac + 2][ar] = av.z; As[ac + 3][ar] = av.w;
        *(float4*)&Bs[br][bc] = bv;
        __syncthreads();
        int kn = kk + BK;
        if (kn < HEXP) {
            if (arow_ok) av = *(const float4*)(Aptr + kn);
            bv = *(const float4*)(Bp + (size_t)(kn + br) * DMODEL + bc);
        }
#pragma unroll
        for (int k = 0; k < BK; k++) {
            float4 a = *(const float4*)&As[k][tm0];
            float4 b = *(const float4*)&Bs[k][tn0];
            u64 bp0 = packf2(b.x, b.y), bp1 = packf2(b.z, b.w);
            u64 a2[4];
            a2[0] = splat2(a.x); a2[1] = splat2(a.y);
            a2[2] = splat2(a.z); a2[3] = splat2(a.w);
#pragma unroll
            for (int i = 0; i < 4; i++) {
                fma2(acc[i][0], a2[i], bp0);
                fma2(acc[i][1], a2[i], bp1);
            }
        }
        __syncthreads();
    }
#pragma unroll
    for (int i = 0; i < 4; i++) {
        int r = tm0 + i;
        if (m0 + r < ne) {
            int   tk = stok[r];
            float w  = sgate[r];
            float* op = out + (size_t)tk * DMODEL + n0 + tn0;
            float2 c0 = unpack2(acc[i][0]), c1 = unpack2(acc[i][1]);
            atomicAdd(op + 0, w * c0.x);
            atomicAdd(op + 1, w * c0.y);
            atomicAdd(op + 2, w * c1.x);
            atomicAdd(op + 3, w * c1.y);
        }
    }
}

// ---------------- GEMM1 shared expert: Hs = silu(X@Ws1)*(X@Ws3) ------------
// grid: (HSH/BN=22, NTOK/BM=64)
__global__ __launch_bounds__(NTHREADS)
void gemm1_shared(const float* __restrict__ x,
                  const float* __restrict__ Ws1,
                  const float* __restrict__ Ws3) {
    int m0 = blockIdx.y * BM;
    int n0 = blockIdx.x * BN;

    __shared__ float As[BK][BM + 4];
    __shared__ float Bs1[BK][BN];
    __shared__ float Bs3[BK][BN];

    int tid = threadIdx.x;
    const float* B1 = Ws1 + n0;
    const float* B3 = Ws3 + n0;

    int ar = tid >> 2, ac = (tid & 3) * 4;
    int br = tid >> 4, bc = (tid & 15) * 4;
    const float* Aptr = x + (size_t)(m0 + ar) * DMODEL + ac;

    float4 av  = *(const float4*)Aptr;
    float4 b1v = *(const float4*)(B1 + (size_t)br * HSH + bc);
    float4 b3v = *(const float4*)(B3 + (size_t)br * HSH + bc);

    int tm0 = (tid >> 4) * 4, tn0 = (tid & 15) * 4;
    u64 acc1[4][2], acc3[4][2];
#pragma unroll
    for (int i = 0; i < 4; i++)
#pragma unroll
        for (int j = 0; j < 2; j++) { acc1[i][j] = 0ull; acc3[i][j] = 0ull; }

    for (int kk = 0; kk < DMODEL; kk += BK) {
        As[ac + 0][ar] = av.x; As[ac + 1][ar] = av.y;
        As[ac + 2][ar] = av.z; As[ac + 3][ar] = av.w;
        *(float4*)&Bs1[br][bc] = b1v;
        *(float4*)&Bs3[br][bc] = b3v;
        __syncthreads();
        int kn = kk + BK;
        if (kn < DMODEL) {
            av  = *(const float4*)(Aptr + kn);
            b1v = *(const float4*)(B1 + (size_t)(kn + br) * HSH + bc);
            b3v = *(const float4*)(B3 + (size_t)(kn + br) * HSH + bc);
        }
#pragma unroll
        for (int k = 0; k < BK; k++) {
            float4 a  = *(const float4*)&As[k][tm0];
            float4 b1 = *(const float4*)&Bs1[k][tn0];
            float4 b3 = *(const float4*)&Bs3[k][tn0];
            u64 b1p0 = packf2(b1.x, b1.y), b1p1 = packf2(b1.z, b1.w);
            u64 b3p0 = packf2(b3.x, b3.y), b3p1 = packf2(b3.z, b3.w);
            u64 a2[4];
            a2[0] = splat2(a.x); a2[1] = splat2(a.y);
            a2[2] = splat2(a.z); a2[3] = splat2(a.w);
#pragma unroll
            for (int i = 0; i < 4; i++) {
                fma2(acc1[i][0], a2[i], b1p0);
                fma2(acc1[i][1], a2[i], b1p1);
                fma2(acc3[i][0], a2[i], b3p0);
                fma2(acc3[i][1], a2[i], b3p1);
            }
        }
        __syncthreads();
    }
#pragma unroll
    for (int i = 0; i < 4; i++) {
        int r = tm0 + i;
        float2 h0 = unpack2(acc1[i][0]), h1 = unpack2(acc1[i][1]);
        float2 q0 = unpack2(acc3[i][0]), q1 = unpack2(acc3[i][1]);
        float4 hv;
        hv.x = silu_f(h0.x) * q0.x;
        hv.y = silu_f(h0.y) * q0.y;
        hv.z = silu_f(h1.x) * q1.x;
        hv.w = silu_f(h1.y) * q1.y;
        *(float4*)&g_hid_s[(size_t)(m0 + r) * HSH + n0 + tn0] = hv;
    }
}

// ---------------- GEMM2 shared expert: out = Hs @ Ws2 (plain write) --------
// grid: (DMODEL/BN=16, NTOK/BM=64)
__global__ __launch_bounds__(NTHREADS)
void gemm2_shared(const float* __restrict__ Ws2, float* __restrict__ out) {
    int m0 = blockIdx.y * BM;
    int n0 = blockIdx.x * BN;

    __shared__ float As[BK][BM + 4];
    __shared__ float Bs[BK][BN];

    int tid = threadIdx.x;
    const float* Bp = Ws2 + n0;

    int ar = tid >> 2, ac = (tid & 3) * 4;
    int br = tid >> 4, bc = (tid & 15) * 4;
    const float* Aptr = g_hid_s + (size_t)(m0 + ar) * HSH + ac;

    float4 av = *(const float4*)Aptr;
    float4 bv = *(const float4*)(Bp + (size_t)br * DMODEL + bc);

    int tm0 = (tid >> 4) * 4, tn0 = (tid & 15) * 4;
    u64 acc[4][2];
#pragma unroll
    for (int i = 0; i < 4; i++) { acc[i][0] = 0ull; acc[i][1] = 0ull; }

    for (int kk = 0; kk < HSH; kk += BK) {
        As[ac + 0][ar] = av.x; As[ac + 1][ar] = av.y;
        As[ac + 2][ar] = av.z; As[ac + 3][ar] = av.w;
        *(float4*)&Bs[br][bc] = bv;
        __syncthreads();
        int kn = kk + BK;
        if (kn < HSH) {
            av = *(const float4*)(Aptr + kn);
            bv = *(const float4*)(Bp + (size_t)(kn + br) * DMODEL + bc);
        }
#pragma unroll
        for (int k = 0; k < BK; k++) {
            float4 a = *(const float4*)&As[k][tm0];
            float4 b = *(const float4*)&Bs[k][tn0];
            u64 bp0 = packf2(b.x, b.y), bp1 = packf2(b.z, b.w);
            u64 a2[4];
            a2[0] = splat2(a.x); a2[1] = splat2(a.y);
            a2[2] = splat2(a.z); a2[3] = splat2(a.w);
#pragma unroll
            for (int i = 0; i < 4; i++) {
                fma2(acc[i][0], a2[i], bp0);
                fma2(acc[i][1], a2[i], bp1);
            }
        }
        __syncthreads();
    }
#pragma unroll
    for (int i = 0; i < 4; i++) {
        int r = tm0 + i;
        float2 c0 = unpack2(acc[i][0]), c1 = unpack2(acc[i][1]);
        float4 ov = make_float4(c0.x, c0.y, c1.x, c1.y);
        *(float4*)&out[(size_t)(m0 + r) * DMODEL + n0 + tn0] = ov;
    }
}

// ---------------- launch ----------------------------------------------------
extern "C" void kernel_launch(void* const* d_in, const int* in_sizes, int n_in,
                              void* d_out, int out_size) {
    const float* x   = (const float*)d_in[0];
    const float* Wg  = (const float*)d_in[1];
    const float* W1  = (const float*)d_in[2];
    const float* W3  = (const float*)d_in[3];
    const float* W2  = (const float*)d_in[4];
    const float* Ws1 = (const float*)d_in[5];
    const float* Ws3 = (const float*)d_in[6];
    const float* Ws2 = (const float*)d_in[7];
    float* out = (float*)d_out;

    zero_kernel<<<1, 32>>>();
    router_kernel<<<NTOK / 8, 256>>>(x, Wg);   // 8 warps/block, 1 token/warp
    scan_kernel<<<1, 1>>>();
    fill_kernel<<<NTOK / 256, 256>>>();

    // shared expert (writes every element of out) must precede routed scatter
    gemm1_shared<<<dim3(HSH / BN, NTOK / BM), NTHREADS>>>(x, Ws1, Ws3);
    gemm2_shared<<<dim3(DMODEL / BN, NTOK / BM), NTHREADS>>>(Ws2, out);

    gemm1_routed<<<dim3(HEXP / BN, NTOK / BM, NEXP), NTHREADS>>>(x, W1, W3);
    gemm2_routed<<<dim3(DMODEL / BN, NTOK / BM, NEXP), NTHREADS>>>(W2, out);
}